// round 3
// baseline (speedup 1.0000x reference)
#include <cuda_runtime.h>

// Encoder_82910048682485 — R2: packed f32x2 FMA + 2 CTAs/SM + cp.async
// double-buffered weight slabs.
//
// Level structure: children of parents [p0, p0+n) are the contiguous slab
// [2p0+1, 2p0+2n] -> each level is a fused 2-layer MLP on contiguous memory.
//
// Per-level kernel (template BM rows/block, 256 threads):
//   sX [BM][260]  : X tile, later overwritten with H (layer-1 output)
//   sW [2][16][256]: double-buffered weight slabs (BK=16 k-rows)
//   Layer1 accumulators (both 128-col chunks) live entirely in registers
//   (2 x RPT x 4 f32x2), so no separate H smem buffer -> 97KB smem -> 2 CTAs/SM.
//   All FMAs are fma.rn.f32x2 (2 columns per issue).

using ull = unsigned long long;

static __forceinline__ __device__ float lrelu(float v) {
    return v > 0.0f ? v : 0.01f * v;
}

static __forceinline__ __device__ ull pack2(float x) {
    ull r; asm("mov.b64 %0, {%1, %1};" : "=l"(r) : "f"(x)); return r;
}
static __forceinline__ __device__ ull pack2(float x, float y) {
    ull r; asm("mov.b64 %0, {%1, %2};" : "=l"(r) : "f"(x), "f"(y)); return r;
}
static __forceinline__ __device__ void unpack2(ull v, float& x, float& y) {
    asm("mov.b64 {%0, %1}, %2;" : "=f"(x), "=f"(y) : "l"(v));
}
static __forceinline__ __device__ void ffma2(ull& d, ull a, ull b) {
    asm("fma.rn.f32x2 %0, %1, %2, %0;" : "+l"(d) : "l"(a), "l"(b));
}
static __forceinline__ __device__ void lds_v2u64(unsigned addr, ull& a, ull& b) {
    asm volatile("ld.shared.v2.u64 {%0, %1}, [%2];" : "=l"(a), "=l"(b) : "r"(addr));
}
static __forceinline__ __device__ void cp16(unsigned dst, const void* src) {
    asm volatile("cp.async.cg.shared.global [%0], [%1], 16;" :: "r"(dst), "l"(src));
}
#define CP_COMMIT() asm volatile("cp.async.commit_group;")
#define CP_WAIT0()  asm volatile("cp.async.wait_group 0;")

constexpr int DEPTH = 18;

template<int BM>
__global__ void __launch_bounds__(256, 2)
mlp_level_kernel(const float* __restrict__ X, float* __restrict__ Y,
                 const float* __restrict__ W1, const float* __restrict__ b1,
                 const float* __restrict__ W2, const float* __restrict__ b2,
                 int n)
{
    constexpr int RPT = BM / 16;                 // rows per thread
    extern __shared__ float smem[];
    float* sX = smem;                            // [BM][260]
    float* sW = smem + BM * 260;                 // [2][16][256]

    const int tid  = threadIdx.x;
    const int tx   = tid & 15;                   // 16 col groups of 8 (within 128-chunk)
    const int ty   = tid >> 4;                   // 16 row groups of RPT
    const int row0 = blockIdx.x * BM;

    const unsigned sW_base = (unsigned)__cvta_generic_to_shared(sW);

    // ---- prologue: async-load W1 slab 0 into buf 0 (overlaps X-tile load) ----
    {
        const char* src = (const char*)W1 + (size_t)tid * 16;
        unsigned dst = sW_base + tid * 16;
        #pragma unroll
        for (int j = 0; j < 4; ++j) cp16(dst + j * 4096, src + j * 4096);
        CP_COMMIT();
    }

    // ---- X tile [BM,256] (zero-fill rows >= n) ----
    for (int idx = tid; idx < BM * 64; idx += 256) {
        int r = idx >> 6, c4 = idx & 63;
        float4 v = make_float4(0.f, 0.f, 0.f, 0.f);
        if (row0 + r < n)
            v = reinterpret_cast<const float4*>(X)[(size_t)(row0 + r) * 64 + c4];
        *reinterpret_cast<float4*>(&sX[r * 260 + c4 * 4]) = v;
    }

    // ---- layer-1 accumulators: both 128-col chunks, in registers ----
    ull acc[2][RPT][4];
    #pragma unroll
    for (int c = 0; c < 2; ++c) {
        float4 v0 = *reinterpret_cast<const float4*>(b1 + c * 128 + tx * 8);
        float4 v1 = *reinterpret_cast<const float4*>(b1 + c * 128 + tx * 8 + 4);
        #pragma unroll
        for (int i = 0; i < RPT; ++i) {
            acc[c][i][0] = pack2(v0.x, v0.y);
            acc[c][i][1] = pack2(v0.z, v0.w);
            acc[c][i][2] = pack2(v1.x, v1.y);
            acc[c][i][3] = pack2(v1.z, v1.w);
        }
    }

    int buf = 0;
    // ---- layer 1: 16 slabs of BK=16 over K=256 ----
    for (int s = 0; s < 16; ++s) {
        CP_WAIT0();
        __syncthreads();
        {   // prefetch next slab into buf^1 (slab 15 prefetches W2 slab 0)
            unsigned dstb = sW_base + (buf ^ 1) * 16384 + tid * 16;
            if (s < 15) {
                const char* src = (const char*)W1 + (size_t)(s + 1) * 16384 + tid * 16;
                #pragma unroll
                for (int j = 0; j < 4; ++j) cp16(dstb + j * 4096, src + j * 4096);
            } else {
                const char* src = (const char*)W2 + (size_t)tid * 16;
                #pragma unroll
                for (int j = 0; j < 2; ++j) cp16(dstb + j * 4096, src + j * 4096);
            }
            CP_COMMIT();
        }
        const int kbase = s * 16;
        #pragma unroll
        for (int kk = 0; kk < 16; ++kk) {
            ull apk[RPT];
            #pragma unroll
            for (int i = 0; i < RPT; ++i)
                apk[i] = pack2(sX[(ty * RPT + i) * 260 + kbase + kk]);
            unsigned wrow = sW_base + buf * 16384 + kk * 1024 + tx * 32;
            ull w00, w01, w02, w03, w10, w11, w12, w13;
            lds_v2u64(wrow,        w00, w01);
            lds_v2u64(wrow + 16,   w02, w03);
            lds_v2u64(wrow + 512,  w10, w11);
            lds_v2u64(wrow + 528,  w12, w13);
            #pragma unroll
            for (int i = 0; i < RPT; ++i) {
                ffma2(acc[0][i][0], apk[i], w00);
                ffma2(acc[0][i][1], apk[i], w01);
                ffma2(acc[0][i][2], apk[i], w02);
                ffma2(acc[0][i][3], apk[i], w03);
                ffma2(acc[1][i][0], apk[i], w10);
                ffma2(acc[1][i][1], apk[i], w11);
                ffma2(acc[1][i][2], apk[i], w12);
                ffma2(acc[1][i][3], apk[i], w13);
            }
        }
        buf ^= 1;
    }

    // ---- H = lrelu(acc) overwrites sX (X rows only touched by same ty-group) ----
    __syncthreads();
    #pragma unroll
    for (int c = 0; c < 2; ++c)
        #pragma unroll
        for (int i = 0; i < RPT; ++i) {
            float4 o0, o1; float x, y;
            unpack2(acc[c][i][0], x, y); o0.x = lrelu(x); o0.y = lrelu(y);
            unpack2(acc[c][i][1], x, y); o0.z = lrelu(x); o0.w = lrelu(y);
            unpack2(acc[c][i][2], x, y); o1.x = lrelu(x); o1.y = lrelu(y);
            unpack2(acc[c][i][3], x, y); o1.z = lrelu(x); o1.w = lrelu(y);
            float* p = &sX[(ty * RPT + i) * 260 + c * 128 + tx * 8];
            *reinterpret_cast<float4*>(p)     = o0;
            *reinterpret_cast<float4*>(p + 4) = o1;
        }
    // visibility of H across threads is covered by the sync at top of layer-2 s=0

    // ---- layer-2 accumulators ----
    ull acc2[RPT][4];
    {
        float4 v0 = *reinterpret_cast<const float4*>(b2 + tx * 8);
        float4 v1 = *reinterpret_cast<const float4*>(b2 + tx * 8 + 4);
        #pragma unroll
        for (int i = 0; i < RPT; ++i) {
            acc2[i][0] = pack2(v0.x, v0.y);
            acc2[i][1] = pack2(v0.z, v0.w);
            acc2[i][2] = pack2(v1.x, v1.y);
            acc2[i][3] = pack2(v1.z, v1.w);
        }
    }

    // ---- layer 2: 16 slabs of BK=16 over K=256, N=128 ----
    for (int s = 0; s < 16; ++s) {
        CP_WAIT0();
        __syncthreads();
        if (s < 15) {
            unsigned dstb = sW_base + (buf ^ 1) * 16384 + tid * 16;
            const char* src = (const char*)W2 + (size_t)(s + 1) * 8192 + tid * 16;
            #pragma unroll
            for (int j = 0; j < 2; ++j) cp16(dstb + j * 4096, src + j * 4096);
            CP_COMMIT();
        }
        const int kbase = s * 16;
        #pragma unroll
        for (int kk = 0; kk < 16; ++kk) {
            ull apk[RPT];
            #pragma unroll
            for (int i = 0; i < RPT; ++i)
                apk[i] = pack2(sX[(ty * RPT + i) * 260 + kbase + kk]);
            unsigned wrow = sW_base + buf * 16384 + kk * 512 + tx * 32;
            ull w0, w1, w2, w3;
            lds_v2u64(wrow,      w0, w1);
            lds_v2u64(wrow + 16, w2, w3);
            #pragma unroll
            for (int i = 0; i < RPT; ++i) {
                ffma2(acc2[i][0], apk[i], w0);
                ffma2(acc2[i][1], apk[i], w1);
                ffma2(acc2[i][2], apk[i], w2);
                ffma2(acc2[i][3], apk[i], w3);
            }
        }
        buf ^= 1;
    }

    // ---- store Y = lrelu(acc2) ----
    #pragma unroll
    for (int i = 0; i < RPT; ++i) {
        int r = row0 + ty * RPT + i;
        if (r < n) {
            float4 o0, o1; float x, y;
            unpack2(acc2[i][0], x, y); o0.x = lrelu(x); o0.y = lrelu(y);
            unpack2(acc2[i][1], x, y); o0.z = lrelu(x); o0.w = lrelu(y);
            unpack2(acc2[i][2], x, y); o1.x = lrelu(x); o1.y = lrelu(y);
            unpack2(acc2[i][3], x, y); o1.z = lrelu(x); o1.w = lrelu(y);
            float* p = Y + (size_t)r * 128 + tx * 8;
            *reinterpret_cast<float4*>(p)     = o0;
            *reinterpret_cast<float4*>(p + 4) = o1;
        }
    }
}

constexpr int SMEM64 = 64 * 260 * 4 + 2 * 16 * 256 * 4;   // 99328
constexpr int SMEM16 = 16 * 260 * 4 + 2 * 16 * 256 * 4;   // 49408

// Leaf embedder: Y[i] = lrelu(L[i,:32] @ We + be). 64 rows/block, K=32.
__global__ void __launch_bounds__(256, 1) leaf_kernel(
    const float* __restrict__ L, const float* __restrict__ We,
    const float* __restrict__ be, float* __restrict__ Y)
{
    __shared__ float sL[64 * 36];
    __shared__ float sW[32 * 128];

    const int tid = threadIdx.x;
    const int tx = tid & 15;
    const int ty = tid >> 4;
    const size_t row0 = (size_t)blockIdx.x * 64;

    for (int idx = tid; idx < 512; idx += 256) {
        int r = idx >> 3, c4 = idx & 7;
        float4 v = reinterpret_cast<const float4*>(L + (row0 + r) * 32)[c4];
        *reinterpret_cast<float4*>(&sL[r * 36 + c4 * 4]) = v;
    }
    for (int idx = tid; idx < 1024; idx += 256)
        reinterpret_cast<float4*>(sW)[idx] = reinterpret_cast<const float4*>(We)[idx];
    __syncthreads();

    ull acc[4][4];
    {
        float4 v0 = *reinterpret_cast<const float4*>(be + tx * 8);
        float4 v1 = *reinterpret_cast<const float4*>(be + tx * 8 + 4);
        #pragma unroll
        for (int i = 0; i < 4; ++i) {
            acc[i][0] = pack2(v0.x, v0.y);
            acc[i][1] = pack2(v0.z, v0.w);
            acc[i][2] = pack2(v1.x, v1.y);
            acc[i][3] = pack2(v1.z, v1.w);
        }
    }
    const unsigned sW_base = (unsigned)__cvta_generic_to_shared(sW);
    #pragma unroll
    for (int k = 0; k < 32; ++k) {
        unsigned wrow = sW_base + k * 512 + tx * 32;
        ull w0, w1, w2, w3;
        lds_v2u64(wrow,      w0, w1);
        lds_v2u64(wrow + 16, w2, w3);
        #pragma unroll
        for (int i = 0; i < 4; ++i) {
            ull a = pack2(sL[(ty * 4 + i) * 36 + k]);
            ffma2(acc[i][0], a, w0);
            ffma2(acc[i][1], a, w1);
            ffma2(acc[i][2], a, w2);
            ffma2(acc[i][3], a, w3);
        }
    }
    #pragma unroll
    for (int i = 0; i < 4; ++i) {
        size_t r = row0 + ty * 4 + i;
        float4 o0, o1; float x, y;
        unpack2(acc[i][0], x, y); o0.x = lrelu(x); o0.y = lrelu(y);
        unpack2(acc[i][1], x, y); o0.z = lrelu(x); o0.w = lrelu(y);
        unpack2(acc[i][2], x, y); o1.x = lrelu(x); o1.y = lrelu(y);
        unpack2(acc[i][3], x, y); o1.z = lrelu(x); o1.w = lrelu(y);
        reinterpret_cast<float4*>(Y + r * 128 + tx * 8)[0] = o0;
        reinterpret_cast<float4*>(Y + r * 128 + tx * 8)[1] = o1;
    }
}

extern "C" void kernel_launch(void* const* d_in, const int* in_sizes, int n_in,
                              void* d_out, int out_size)
{
    const float* leaf = (const float*)d_in[0];
    const float* We   = (const float*)d_in[1];
    const float* be   = (const float*)d_in[2];
    const float* W1   = (const float*)d_in[3];
    const float* b1   = (const float*)d_in[4];
    const float* W2   = (const float*)d_in[5];
    const float* b2   = (const float*)d_in[6];
    float* out = (float*)d_out;

    cudaFuncSetAttribute(mlp_level_kernel<64>,
                         cudaFuncAttributeMaxDynamicSharedMemorySize, SMEM64);
    cudaFuncSetAttribute(mlp_level_kernel<16>,
                         cudaFuncAttributeMaxDynamicSharedMemorySize, SMEM16);

    const size_t leaf_start = (size_t)(1u << DEPTH) - 1;
    leaf_kernel<<<(1 << DEPTH) / 64, 256>>>(leaf, We, be, out + leaf_start * 128);

    for (int l = DEPTH - 1; l >= 0; --l) {
        const int n = 1 << l;
        const size_t p0 = (size_t)(1u << l) - 1;
        const float* X = out + (2 * p0 + 1) * 128;
        float* Y = out + p0 * 128;
        if (n >= 16384) {
            mlp_level_kernel<64><<<n / 64, 256, SMEM64>>>(X, Y, W1, b1, W2, b2, n);
        } else {
            mlp_level_kernel<16><<<(n + 15) / 16, 256, SMEM16>>>(X, Y, W1, b1, W2, b2, n);
        }
    }
}

// round 5
// speedup vs baseline: 2.9110x; 2.9110x over previous
#include <cuda_runtime.h>
#include <cuda_bf16.h>
#include <cstdint>

// R5: warp-level mma.sync bf16 split-2 fused 2-layer MLP (base-target PTX; no tcgen05).
// x*w ~= xhi*whi + xlo*whi + xhi*wlo, fp32 accumulate.

static __forceinline__ __device__ float lrelu(float v) { return v > 0.0f ? v : 0.01f * v; }

constexpr int DEPTH = 18;
// smem byte map (level kernel)
constexpr int SA_HI = 0;          // [64][264] bf16 = 33792
constexpr int SA_LO = 33792;      // 33792
constexpr int W_ST  = 67584;      // 2 stages x 16896 (hi[16][264] + lo[16][264])
constexpr int SB1   = 101376;     // 1024
constexpr int SB2   = 102400;     // 512
constexpr int SMEM_LVL = 102912;

// pre-split weights: W1 [256][256] hi/lo, W2 [256][128] hi/lo (row-major bf16)
__device__ __align__(16) __nv_bfloat16 W1hi_d[65536];
__device__ __align__(16) __nv_bfloat16 W1lo_d[65536];
__device__ __align__(16) __nv_bfloat16 W2hi_d[32768];
__device__ __align__(16) __nv_bfloat16 W2lo_d[32768];

static __forceinline__ __device__ uint32_t smem_u32(const void* p) {
    uint32_t a;
    asm("{ .reg .u64 t; cvta.to.shared.u64 t, %1; cvt.u32.u64 %0, t; }" : "=r"(a) : "l"(p));
    return a;
}
static __forceinline__ __device__ void cp16(uint32_t d, const void* s) {
    asm volatile("cp.async.cg.shared.global [%0], [%1], 16;" :: "r"(d), "l"(s));
}
#define CP_COMMIT() asm volatile("cp.async.commit_group;" ::: "memory")
#define CP_WAIT(N)  asm volatile("cp.async.wait_group %0;" :: "n"(N) : "memory")

static __forceinline__ __device__ void ldsm4(unsigned* r, uint32_t a) {
    asm volatile("ldmatrix.sync.aligned.m8n8.x4.shared.b16 {%0,%1,%2,%3}, [%4];"
                 : "=r"(r[0]), "=r"(r[1]), "=r"(r[2]), "=r"(r[3]) : "r"(a));
}
static __forceinline__ __device__ void ldsm4t(unsigned* r, uint32_t a) {
    asm volatile("ldmatrix.sync.aligned.m8n8.x4.trans.shared.b16 {%0,%1,%2,%3}, [%4];"
                 : "=r"(r[0]), "=r"(r[1]), "=r"(r[2]), "=r"(r[3]) : "r"(a));
}
static __forceinline__ __device__ void mma_bf16(float* c, const unsigned* a, const unsigned* b) {
    asm volatile("mma.sync.aligned.m16n8k16.row.col.f32.bf16.bf16.f32 "
                 "{%0,%1,%2,%3}, {%4,%5,%6,%7}, {%8,%9}, {%0,%1,%2,%3};"
                 : "+f"(c[0]), "+f"(c[1]), "+f"(c[2]), "+f"(c[3])
                 : "r"(a[0]), "r"(a[1]), "r"(a[2]), "r"(a[3]), "r"(b[0]), "r"(b[1]));
}
static __forceinline__ __device__ void split2(float h0, float h1,
                                              __nv_bfloat162& hi, __nv_bfloat162& lo) {
    hi = __floats2bfloat162_rn(h0, h1);
    lo = __floats2bfloat162_rn(h0 - __bfloat162float(hi.x), h1 - __bfloat162float(hi.y));
}

__global__ void prep_kernel(const float* __restrict__ W1, const float* __restrict__ W2) {
    int t = blockIdx.x * 256 + threadIdx.x;
    if (t < 65536) {
        float f = W1[t];
        __nv_bfloat16 hi = __float2bfloat16(f);
        W1hi_d[t] = hi;
        W1lo_d[t] = __float2bfloat16(f - __bfloat162float(hi));
    }
    if (t < 32768) {
        float f = W2[t];
        __nv_bfloat16 hi = __float2bfloat16(f);
        W2hi_d[t] = hi;
        W2lo_d[t] = __float2bfloat16(f - __bfloat162float(hi));
    }
}

// slab g: 0-15 -> W1 ktile g (16 k-rows x 256 n), 16-31 -> W2 ktile g-16 (16 x 128)
static __forceinline__ __device__ void load_slab(int g, uint32_t base, int tid) {
    uint32_t stage = base + W_ST + (uint32_t)(g & 1) * 16896u;
    if (g < 16) {
        #pragma unroll
        for (int j = 0; j < 2; ++j) {
            int idx = tid + j * 256;            // 512 chunks
            int r = idx >> 5, c = idx & 31;
            uint32_t d = stage + r * 528 + c * 16;
            size_t so = (size_t)(g * 16 + r) * 512 + c * 16;
            cp16(d,        (const char*)W1hi_d + so);
            cp16(d + 8448, (const char*)W1lo_d + so);
        }
    } else {
        int r = tid >> 4, c = tid & 15;         // 256 chunks
        uint32_t d = stage + r * 272 + c * 16;
        size_t so = (size_t)((g - 16) * 16 + r) * 256 + c * 16;
        cp16(d,        (const char*)W2hi_d + so);
        cp16(d + 4352, (const char*)W2lo_d + so);
    }
    CP_COMMIT();
}

__global__ void __launch_bounds__(256, 2)
level_kernel(const float* __restrict__ X, float* __restrict__ Y,
             const float* __restrict__ b1, const float* __restrict__ b2, int n)
{
    extern __shared__ __align__(16) char sm[];
    const uint32_t base = smem_u32(sm);
    const int tid = threadIdx.x;
    const int wid = tid >> 5, lane = tid & 31;
    const int wr = (wid & 3) * 16;              // warp row base (0..48)
    const int nh = wid >> 2;                    // n-half (0/1)
    const int row0 = blockIdx.x * 64;
    const int lrow = lane & 15;                 // ldmatrix address row within 16
    const int lcol8 = (lane >> 4) * 8;          // ldmatrix address col offset
    const int qr = lane >> 2;                   // frag row within 8
    const int qc = (lane & 3) * 2;              // frag col pair

    // prologue: first two weight slabs
    load_slab(0, base, tid);
    load_slab(1, base, tid);

    ((float*)(sm + SB1))[tid] = b1[tid];
    if (tid < 128) ((float*)(sm + SB2))[tid] = b2[tid];

    // X tile [64][256] load + hi/lo split into sA (stride 264 bf16)
    for (int idx = tid; idx < 64 * 64; idx += 256) {
        int r = idx >> 6, c4 = idx & 63;
        float4 v = make_float4(0.f, 0.f, 0.f, 0.f);
        if (row0 + r < n)
            v = reinterpret_cast<const float4*>(X)[(size_t)(row0 + r) * 64 + c4];
        __nv_bfloat162 h0, l0, h1, l1;
        split2(v.x, v.y, h0, l0);
        split2(v.z, v.w, h1, l1);
        uint32_t off = (uint32_t)r * 528 + c4 * 8;
        *(__nv_bfloat162*)(sm + SA_HI + off)     = h0;
        *(__nv_bfloat162*)(sm + SA_HI + off + 4) = h1;
        *(__nv_bfloat162*)(sm + SA_LO + off)     = l0;
        *(__nv_bfloat162*)(sm + SA_LO + off + 4) = l1;
    }

    const float* sB1 = (const float*)(sm + SB1);
    const float* sB2 = (const float*)(sm + SB2);

    // accumulators
    float acc1[16][4];   // layer1: 16 ntiles x 8 cols over this warp's 128-col half
    float acc2[8][4];    // layer2: 8 ntiles over 64-col half
    #pragma unroll
    for (int t = 0; t < 16; ++t) {
        float bb0 = sB1[nh * 128 + t * 8 + qc], bb1 = sB1[nh * 128 + t * 8 + qc + 1];
        acc1[t][0] = bb0; acc1[t][1] = bb1; acc1[t][2] = bb0; acc1[t][3] = bb1;
    }
    #pragma unroll
    for (int t = 0; t < 8; ++t) {
        float bb0 = sB2[nh * 64 + t * 8 + qc], bb1 = sB2[nh * 64 + t * 8 + qc + 1];
        acc2[t][0] = bb0; acc2[t][1] = bb1; acc2[t][2] = bb0; acc2[t][3] = bb1;
    }

    const uint32_t aHi = base + SA_HI + (uint32_t)(wr + lrow) * 528;
    const uint32_t aLo = base + SA_LO + (uint32_t)(wr + lrow) * 528;

    for (int g = 0; g < 32; ++g) {
        if (g == 16) {
            // epilogue 1: acc1 -> H (lrelu, split) back into sA at this warp's tile
            #pragma unroll
            for (int t = 0; t < 16; ++t) {
                int col = nh * 128 + t * 8 + qc;
                __nv_bfloat162 hi2, lo2;
                split2(lrelu(acc1[t][0]), lrelu(acc1[t][1]), hi2, lo2);
                uint32_t o0 = (uint32_t)(wr + qr) * 528 + col * 2;
                *(__nv_bfloat162*)(sm + SA_HI + o0) = hi2;
                *(__nv_bfloat162*)(sm + SA_LO + o0) = lo2;
                split2(lrelu(acc1[t][2]), lrelu(acc1[t][3]), hi2, lo2);
                uint32_t o1 = (uint32_t)(wr + qr + 8) * 528 + col * 2;
                *(__nv_bfloat162*)(sm + SA_HI + o1) = hi2;
                *(__nv_bfloat162*)(sm + SA_LO + o1) = lo2;
            }
        }
        if (g < 31) { CP_WAIT(1); } else { CP_WAIT(0); }
        __syncthreads();   // slab g ready; H visible for layer2; prev stage free

        const uint32_t stage = base + W_ST + (uint32_t)(g & 1) * 16896u;
        if (g < 16) {
            unsigned ahi[4], alo[4];
            ldsm4(ahi, aHi + (uint32_t)(g * 16 + lcol8) * 2);
            ldsm4(alo, aLo + (uint32_t)(g * 16 + lcol8) * 2);
            uint32_t brow = stage + (uint32_t)lrow * 528;
            #pragma unroll
            for (int p = 0; p < 8; ++p) {
                int nb = nh * 128 + p * 16;
                unsigned bhi[4], blo[4];
                ldsm4t(bhi, brow + (uint32_t)(nb + lcol8) * 2);
                ldsm4t(blo, brow + 8448 + (uint32_t)(nb + lcol8) * 2);
                mma_bf16(acc1[2 * p],     ahi, bhi);
                mma_bf16(acc1[2 * p + 1], ahi, bhi + 2);
                mma_bf16(acc1[2 * p],     alo, bhi);
                mma_bf16(acc1[2 * p + 1], alo, bhi + 2);
                mma_bf16(acc1[2 * p],     ahi, blo);
                mma_bf16(acc1[2 * p + 1], ahi, blo + 2);
            }
        } else {
            int k0 = (g - 16) * 16;
            unsigned ahi[4], alo[4];
            ldsm4(ahi, aHi + (uint32_t)(k0 + lcol8) * 2);
            ldsm4(alo, aLo + (uint32_t)(k0 + lcol8) * 2);
            uint32_t brow = stage + (uint32_t)lrow * 272;
            #pragma unroll
            for (int p = 0; p < 4; ++p) {
                int nb = nh * 64 + p * 16;
                unsigned bhi[4], blo[4];
                ldsm4t(bhi, brow + (uint32_t)(nb + lcol8) * 2);
                ldsm4t(blo, brow + 4352 + (uint32_t)(nb + lcol8) * 2);
                mma_bf16(acc2[2 * p],     ahi, bhi);
                mma_bf16(acc2[2 * p + 1], ahi, bhi + 2);
                mma_bf16(acc2[2 * p],     alo, bhi);
                mma_bf16(acc2[2 * p + 1], alo, bhi + 2);
                mma_bf16(acc2[2 * p],     ahi, blo);
                mma_bf16(acc2[2 * p + 1], ahi, blo + 2);
            }
        }
        __syncthreads();   // all warps done with slab g (stage reusable)
        if (g + 2 < 32) load_slab(g + 2, base, tid);
    }

    // epilogue 2: Y = lrelu(acc2)
    #pragma unroll
    for (int t = 0; t < 8; ++t) {
        int col = nh * 64 + t * 8 + qc;
        int r0 = row0 + wr + qr;
        if (r0 < n) {
            float2 o = make_float2(lrelu(acc2[t][0]), lrelu(acc2[t][1]));
            *reinterpret_cast<float2*>(Y + (size_t)r0 * 128 + col) = o;
        }
        if (r0 + 8 < n) {
            float2 o = make_float2(lrelu(acc2[t][2]), lrelu(acc2[t][3]));
            *reinterpret_cast<float2*>(Y + (size_t)(r0 + 8) * 128 + col) = o;
        }
    }
}

// leaf: Y = lrelu(L[.,32] @ We + be), fp32 scalar
__global__ void __launch_bounds__(256, 1) leaf_kernel(
    const float* __restrict__ L, const float* __restrict__ We,
    const float* __restrict__ be, float* __restrict__ Y)
{
    __shared__ float sL[64 * 36];
    __shared__ float sW[32 * 128];
    const int tid = threadIdx.x, tx = tid & 15, ty = tid >> 4;
    const size_t row0 = (size_t)blockIdx.x * 64;

    for (int idx = tid; idx < 512; idx += 256) {
        int r = idx >> 3, c4 = idx & 7;
        float4 v = reinterpret_cast<const float4*>(L + (row0 + r) * 32)[c4];
        *reinterpret_cast<float4*>(&sL[r * 36 + c4 * 4]) = v;
    }
    for (int idx = tid; idx < 1024; idx += 256)
        reinterpret_cast<float4*>(sW)[idx] = reinterpret_cast<const float4*>(We)[idx];
    __syncthreads();

    float acc[4][8];
    float4 e0 = *reinterpret_cast<const float4*>(be + tx * 8);
    float4 e1 = *reinterpret_cast<const float4*>(be + tx * 8 + 4);
    #pragma unroll
    for (int i = 0; i < 4; ++i) {
        acc[i][0] = e0.x; acc[i][1] = e0.y; acc[i][2] = e0.z; acc[i][3] = e0.w;
        acc[i][4] = e1.x; acc[i][5] = e1.y; acc[i][6] = e1.z; acc[i][7] = e1.w;
    }
    #pragma unroll 8
    for (int k = 0; k < 32; ++k) {
        float4 b0 = *reinterpret_cast<float4*>(&sW[k * 128 + tx * 8]);
        float4 b1 = *reinterpret_cast<float4*>(&sW[k * 128 + tx * 8 + 4]);
        #pragma unroll
        for (int i = 0; i < 4; ++i) {
            float a = sL[(ty * 4 + i) * 36 + k];
            acc[i][0] = fmaf(a, b0.x, acc[i][0]); acc[i][1] = fmaf(a, b0.y, acc[i][1]);
            acc[i][2] = fmaf(a, b0.z, acc[i][2]); acc[i][3] = fmaf(a, b0.w, acc[i][3]);
            acc[i][4] = fmaf(a, b1.x, acc[i][4]); acc[i][5] = fmaf(a, b1.y, acc[i][5]);
            acc[i][6] = fmaf(a, b1.z, acc[i][6]); acc[i][7] = fmaf(a, b1.w, acc[i][7]);
        }
    }
    #pragma unroll
    for (int i = 0; i < 4; ++i) {
        size_t r = row0 + ty * 4 + i;
        float4 o0, o1;
        o0.x = lrelu(acc[i][0]); o0.y = lrelu(acc[i][1]); o0.z = lrelu(acc[i][2]); o0.w = lrelu(acc[i][3]);
        o1.x = lrelu(acc[i][4]); o1.y = lrelu(acc[i][5]); o1.z = lrelu(acc[i][6]); o1.w = lrelu(acc[i][7]);
        reinterpret_cast<float4*>(Y + r * 128 + tx * 8)[0] = o0;
        reinterpret_cast<float4*>(Y + r * 128 + tx * 8)[1] = o1;
    }
}

extern "C" void kernel_launch(void* const* d_in, const int* in_sizes, int n_in,
                              void* d_out, int out_size)
{
    const float* leaf = (const float*)d_in[0];
    const float* We   = (const float*)d_in[1];
    const float* be   = (const float*)d_in[2];
    const float* W1   = (const float*)d_in[3];
    const float* b1   = (const float*)d_in[4];
    const float* W2   = (const float*)d_in[5];
    const float* b2   = (const float*)d_in[6];
    float* out = (float*)d_out;

    cudaFuncSetAttribute(level_kernel, cudaFuncAttributeMaxDynamicSharedMemorySize, SMEM_LVL);

    prep_kernel<<<256, 256>>>(W1, W2);
    const size_t leaf_start = (size_t)(1u << DEPTH) - 1;
    leaf_kernel<<<(1 << DEPTH) / 64, 256>>>(leaf, We, be, out + leaf_start * 128);

    for (int l = DEPTH - 1; l >= 0; --l) {
        const int n = 1 << l;
        const size_t p0 = (size_t)(1u << l) - 1;
        const float* X = out + (2 * p0 + 1) * 128;
        float* Y = out + p0 * 128;
        level_kernel<<<(n + 63) / 64, 256, SMEM_LVL>>>(X, Y, b1, b2, n);
    }
}